// round 3
// baseline (speedup 1.0000x reference)
#include <cuda_runtime.h>
#include <cstdint>

#define BB   64
#define LL   128
#define TE   256
#define CIN  256
#define HH   512
#define CAT  768
#define G4   2048
#define OUTN 128
#define NBLK 128
#define NTHR 512

// ---------------- persistent device buffers ----------------
__device__ float g_pe[(size_t)BB * TE * HH];   // proj_enc (32 MB)
__device__ float g_pdp[16 * 64 * HH];          // pd split-K partials
__device__ float g_xp[24 * 64 * CIN];          // xhat split-K partials
__device__ float g_zp[8 * 64 * G4];            // lstm-z partials (reused by epilogue O1)
__device__ float g_fp[8 * 64 * 3 * HH];        // cfc partials (reused by epilogue O2)
__device__ float g_h[BB * HH];
__device__ float g_c[BB * HH];
__device__ float g_ctx[BB * HH];
__device__ float g_xhat[BB * CIN];
__device__ float g_hlstm[BB * HH];
__device__ float g_hid[BB * HH];
__device__ float g_w6[G4 * CAT];               // [W_ih | W_hh]
__device__ float g_w3[3 * HH * CAT];           // [W_ff1 ; W_ff2 ; W_ta+W_tb]
__device__ float g_b3[3 * HH];
__device__ unsigned g_bcnt;
__device__ unsigned g_bgen;

// ---------------- helpers ----------------
__device__ __forceinline__ float fast_tanh(float x) {
    float y;
    asm("tanh.approx.f32 %0, %1;" : "=f"(y) : "f"(x));
    return y;
}
__device__ __forceinline__ float sigm(float x) {
    return 1.0f / (1.0f + __expf(-x));
}

// ---------------- global barrier (all NBLK blocks co-resident) ----------------
__device__ __forceinline__ void gsync() {
    __syncthreads();
    if (threadIdx.x == 0) {
        unsigned gen = atomicAdd(&g_bgen, 0u);
        __threadfence();
        if (atomicAdd(&g_bcnt, 1u) == NBLK - 1) {
            g_bcnt = 0;
            __threadfence();
            atomicAdd(&g_bgen, 1u);
        } else {
            while (atomicAdd(&g_bgen, 0u) == gen) { __nanosleep(64); }
        }
        __threadfence();
    }
    __syncthreads();
}

// ---------------- shared memory union ----------------
struct SmemG { float X[32][65]; float W[32][66]; };
struct SmemA { float pds[HH]; float wss[HH]; float se[TE]; float ss[TE]; float red[NTHR]; };
union Smem { SmemG g; SmemA a; };

// ---------------- 64x64 GEMM tile over k-range (klen % 32 == 0) ----------------
// X row m: cols [0,K0) from X0 + m*str0, cols [K0,...) from X1 + m*str1.
// W row-major (wstr = Ktot). Writes dst[m*dstr + n0+n] (+bias[n0+n] if bias).
__device__ void gemm64(const float* __restrict__ X0, int K0, int str0,
                       const float* __restrict__ X1, int str1,
                       const float* __restrict__ W, int wstr, int n0,
                       int kbeg, int klen,
                       float* __restrict__ dst, int dstr,
                       const float* __restrict__ bias, SmemG& s) {
    int tid = threadIdx.x;
    int lr = tid >> 3;            // 0..63 (m row / n row for loads)
    int c8 = tid & 7;             // col group of 4
    int tx = tid & 31;
    int ty = tid >> 5;
    float acc[4][2] = {};
    for (int kb = 0; kb < klen; kb += 32) {
        int kg = kbeg + kb + c8 * 4;
        float4 xv;
        if (kg < K0) xv = *(const float4*)(X0 + (size_t)lr * str0 + kg);
        else         xv = *(const float4*)(X1 + (size_t)lr * str1 + (kg - K0));
        int kk = c8 * 4;
        s.X[kk + 0][lr] = xv.x; s.X[kk + 1][lr] = xv.y;
        s.X[kk + 2][lr] = xv.z; s.X[kk + 3][lr] = xv.w;
        float4 wv = *(const float4*)(W + (size_t)(n0 + lr) * wstr + kbeg + kb + c8 * 4);
        s.W[kk + 0][lr] = wv.x; s.W[kk + 1][lr] = wv.y;
        s.W[kk + 2][lr] = wv.z; s.W[kk + 3][lr] = wv.w;
        __syncthreads();
#pragma unroll
        for (int k = 0; k < 32; k++) {
            float b0 = s.W[k][tx];
            float b1 = s.W[k][tx + 32];
#pragma unroll
            for (int j = 0; j < 4; j++) {
                float a = s.X[k][ty + 16 * j];
                acc[j][0] += a * b0;
                acc[j][1] += a * b1;
            }
        }
        __syncthreads();
    }
#pragma unroll
    for (int j = 0; j < 4; j++) {
        int m = ty + 16 * j;
#pragma unroll
        for (int c = 0; c < 2; c++) {
            int n = tx + 32 * c;
            float v = acc[j][c];
            if (bias) v += bias[n0 + n];
            dst[(size_t)m * dstr + n0 + n] = v;
        }
    }
}

// ---------------- per-batch attention (block handles one batch b) ----------------
__device__ void attention(int b, const float* __restrict__ h_en,
                          const float* __restrict__ w_score, SmemA& a) {
    int tid = threadIdx.x;
    // reduce pd partials (16 slices)
    for (int h = tid; h < HH; h += NTHR) {
        float sacc = 0.0f;
#pragma unroll
        for (int sl = 0; sl < 16; sl++)
            sacc += g_pdp[(size_t)(sl * 64 + b) * HH + h];
        a.pds[h] = sacc;
        a.wss[h] = w_score[h];
    }
    __syncthreads();
    // e scores
    int warp = tid >> 5, lane = tid & 31;
    const float4* pds4 = (const float4*)a.pds;
    const float4* wss4 = (const float4*)a.wss;
#pragma unroll 2
    for (int tt = 0; tt < 16; tt++) {
        int t = warp + 16 * tt;
        const float4* pe4 = (const float4*)(g_pe + ((size_t)b * TE + t) * HH);
        float acc = 0.0f;
#pragma unroll
        for (int i = 0; i < 4; i++) {
            int h4 = lane + 32 * i;
            float4 p = pe4[h4];
            float4 d = pds4[h4];
            float4 w = wss4[h4];
            acc += w.x * fast_tanh(p.x + d.x);
            acc += w.y * fast_tanh(p.y + d.y);
            acc += w.z * fast_tanh(p.z + d.z);
            acc += w.w * fast_tanh(p.w + d.w);
        }
#pragma unroll
        for (int off = 16; off > 0; off >>= 1)
            acc += __shfl_down_sync(0xffffffffu, acc, off);
        if (lane == 0) a.se[t] = acc;
    }
    __syncthreads();
    // softmax over TE=256
    float ev = (tid < TE) ? a.se[tid] : -1e30f;
    a.red[tid] = ev;
    __syncthreads();
    for (int s = 256; s > 0; s >>= 1) {
        if (tid < s) a.red[tid] = fmaxf(a.red[tid], a.red[tid + s]);
        __syncthreads();
    }
    float mx = a.red[0];
    __syncthreads();
    float p = (tid < TE) ? __expf(ev - mx) : 0.0f;
    a.red[tid] = p;
    __syncthreads();
    for (int s = 256; s > 0; s >>= 1) {
        if (tid < s) a.red[tid] += a.red[tid + s];
        __syncthreads();
    }
    float inv = 1.0f / a.red[0];
    if (tid < TE) a.ss[tid] = p * inv;
    __syncthreads();
    // context: ctx[m] = sum_t ss[t] * h_en[b,t,m]
    int m = tid;
    const float* hb = h_en + (size_t)b * TE * HH + m;
    float a0 = 0, a1 = 0, a2 = 0, a3 = 0;
    for (int t = 0; t < TE; t += 4) {
        a0 += a.ss[t + 0] * hb[(size_t)(t + 0) * HH];
        a1 += a.ss[t + 1] * hb[(size_t)(t + 1) * HH];
        a2 += a.ss[t + 2] * hb[(size_t)(t + 2) * HH];
        a3 += a.ss[t + 3] * hb[(size_t)(t + 3) * HH];
    }
    g_ctx[b * HH + m] = (a0 + a1) + (a2 + a3);
}

// ---------------- weight packing (separate small kernel) ----------------
__global__ void k_pack(const float* __restrict__ W_ih, const float* __restrict__ W_hh,
                       const float* __restrict__ W_ff1, const float* __restrict__ W_ff2,
                       const float* __restrict__ W_ta, const float* __restrict__ W_tb,
                       const float* __restrict__ b_ff1, const float* __restrict__ b_ff2,
                       const float* __restrict__ b_ta, const float* __restrict__ b_tb) {
    const int N6 = G4 * CAT;
    const int N3 = 3 * HH * CAT;
    const int NB2 = 3 * HH;
    int total = N6 + N3 + NB2;
    for (int i = blockIdx.x * blockDim.x + threadIdx.x; i < total; i += gridDim.x * blockDim.x) {
        if (i < N6) {
            int n = i / CAT, k = i % CAT;
            g_w6[i] = (k < CIN) ? W_ih[n * CIN + k] : W_hh[n * HH + (k - CIN)];
        } else if (i < N6 + N3) {
            int j = i - N6;
            int n = j / CAT, k = j % CAT;
            int gate = n / HH, u = n % HH;
            float v;
            if (gate == 0)      v = W_ff1[u * CAT + k];
            else if (gate == 1) v = W_ff2[u * CAT + k];
            else                v = W_ta[u * CAT + k] + W_tb[u * CAT + k];
            g_w3[j] = v;
        } else {
            int n = i - N6 - N3;
            int gate = n / HH, u = n % HH;
            g_b3[n] = (gate == 0) ? b_ff1[u % HH] : (gate == 1) ? b_ff2[n - HH] : (b_ta[n - 2 * HH] + b_tb[n - 2 * HH]);
        }
    }
}

// ---------------- the persistent uber-kernel ----------------
__global__ void __launch_bounds__(NTHR, 1)
k_main(const float* __restrict__ x, const float* __restrict__ h_en,
       const float* __restrict__ W_dec, const float* __restrict__ W_enc,
       const float* __restrict__ b_enc, const float* __restrict__ w_score,
       const float* __restrict__ W_yattn, const float* __restrict__ b_yattn,
       const float* __restrict__ b_ih,
       const float* __restrict__ W_o1, const float* __restrict__ b_o1,
       const float* __restrict__ W_o2, const float* __restrict__ b_o2,
       float* __restrict__ out, int write_state) {
    __shared__ Smem sm;
    int bid = blockIdx.x;
    int tid = threadIdx.x;

    // ---- P0: init h,c + proj_enc ----
    {
        int idx = bid * NTHR + tid;
        if (idx < BB * HH) { g_h[idx] = 0.0f; g_c[idx] = 0.0f; }
    }
    for (int j = bid; j < 2048; j += NBLK) {
        int mt = j >> 3, nt = j & 7;
        int m0 = mt * 64, n0 = nt * 64;
        gemm64(h_en + (size_t)m0 * HH, HH, HH, h_en, 0,
               W_enc, HH, n0, 0, HH,
               g_pe + (size_t)m0 * HH, HH, b_enc, sm.g);
    }
    gsync();

    for (int t = 0; t < LL; t++) {
        const float* xt = x + (size_t)t * CIN;
        // ---- S1: pd split-K (128 jobs) + xhat x-part (32 jobs) ----
        for (int j = bid; j < 160; j += NBLK) {
            if (j < 128) {
                int nt = j >> 4, ks = j & 15;
                gemm64(g_h, HH, HH, g_c, HH,
                       W_dec, 1024, nt * 64, ks * 64, 64,
                       g_pdp + (size_t)ks * 64 * HH, HH, nullptr, sm.g);
            } else {
                int q = j - 128;
                int nt = q >> 3, ks = q & 7;
                gemm64(xt, CIN, LL * CIN, xt, 0,
                       W_yattn, CAT, nt * 64, ks * 32, 32,
                       g_xp + (size_t)ks * 64 * CIN, CIN, nullptr, sm.g);
            }
        }
        gsync();
        // ---- S2: attention (blocks 0-63) || lstm-z h-part (blocks 64-127) ----
        if (bid < 64) {
            attention(bid, h_en, w_score, sm.a);
        } else {
            for (int j = bid - 64; j < 128; j += 64) {
                int nt = j >> 2, ks = j & 3;
                gemm64(g_xhat, CIN, CIN, g_h, HH,
                       g_w6, CAT, nt * 64, CIN + ks * 128, 128,
                       g_zp + (size_t)ks * 64 * G4, G4, nullptr, sm.g);
            }
        }
        gsync();
        // ---- S3: xhat ctx-part (64 jobs, slices 8..23) ----
        for (int j = bid; j < 64; j += NBLK) {
            int nt = j >> 4, ks = j & 15;
            gemm64(xt, CIN, LL * CIN, g_ctx, HH,
                   W_yattn, CAT, nt * 64, CIN + ks * 32, 32,
                   g_xp + (size_t)(8 + ks) * 64 * CIN, CIN, nullptr, sm.g);
        }
        gsync();
        // ---- S4: reduce xhat (24 slices) + bias ----
        for (int idx = bid * NTHR + tid; idx < BB * CIN; idx += NBLK * NTHR) {
            int m = idx >> 8, n = idx & 255;
            float s = b_yattn[n];
#pragma unroll
            for (int sl = 0; sl < 24; sl++)
                s += g_xp[(size_t)(sl * 64 + m) * CIN + n];
            g_xhat[idx] = s;
        }
        gsync();
        // ---- S5: lstm-z x-part (128 jobs, slices 4..7) ----
        for (int j = bid; j < 128; j += NBLK) {
            int nt = j >> 2, ks = j & 3;
            gemm64(g_xhat, CIN, CIN, g_h, HH,
                   g_w6, CAT, nt * 64, ks * 64, 64,
                   g_zp + (size_t)(4 + ks) * 64 * G4, G4, nullptr, sm.g);
        }
        gsync();
        // ---- S6: LSTM pointwise ----
        for (int idx = bid * NTHR + tid; idx < BB * HH; idx += NBLK * NTHR) {
            int m = idx >> 9, u = idx & 511;
            float zi = b_ih[u], zg = b_ih[u + 512], zf = b_ih[u + 1024], zo = b_ih[u + 1536];
#pragma unroll
            for (int sl = 0; sl < 8; sl++) {
                const float* p = g_zp + (size_t)(sl * 64 + m) * G4;
                zi += p[u]; zg += p[u + 512]; zf += p[u + 1024]; zo += p[u + 1536];
            }
            float c_old = g_c[idx];
            float nc = c_old * sigm(zf + 1.0f) + tanhf(zi) * sigm(zg);
            g_c[idx] = nc;
            g_hlstm[idx] = tanhf(nc) * sigm(zo);
        }
        gsync();
        // ---- S7: CfC gates GEMM (192 jobs, splitK8 Kpart96) ----
        for (int j = bid; j < 192; j += NBLK) {
            int nt = j >> 3, ks = j & 7;
            gemm64(g_xhat, CIN, CIN, g_hlstm, HH,
                   g_w3, CAT, nt * 64, ks * 96, 96,
                   g_fp + (size_t)ks * 64 * 3 * HH, 3 * HH, nullptr, sm.g);
        }
        gsync();
        // ---- S8: CfC pointwise -> new h ----
        for (int idx = bid * NTHR + tid; idx < BB * HH; idx += NBLK * NTHR) {
            int m = idx >> 9, u = idx & 511;
            float f1 = g_b3[u], f2 = g_b3[u + 512], tt = g_b3[u + 1024];
#pragma unroll
            for (int sl = 0; sl < 8; sl++) {
                const float* p = g_fp + (size_t)(sl * 64 + m) * (3 * HH);
                f1 += p[u]; f2 += p[u + 512]; tt += p[u + 1024];
            }
            float ti = sigm(tt);
            g_h[idx] = tanhf(f1) * (1.0f - ti) + ti * tanhf(f2);
        }
        gsync();
    }

    // ---- E1: O1 GEMM ([h|ctx] K=1024), partials in g_zp (dstr=HH) ----
    for (int j = bid; j < 32; j += NBLK) {
        int nt = j >> 2, ks = j & 3;
        gemm64(g_h, HH, HH, g_ctx, HH,
               W_o1, 1024, nt * 64, ks * 256, 256,
               g_zp + (size_t)ks * 64 * HH, HH, nullptr, sm.g);
    }
    gsync();
    // ---- E2: reduce + leaky relu -> g_hid ----
    for (int idx = bid * NTHR + tid; idx < BB * HH; idx += NBLK * NTHR) {
        int m = idx >> 9, u = idx & 511;
        float s = b_o1[u];
#pragma unroll
        for (int sl = 0; sl < 4; sl++)
            s += g_zp[(size_t)(sl * 64 + m) * HH + u];
        g_hid[idx] = (s > 0.0f) ? s : 0.01f * s;
    }
    gsync();
    // ---- E3: O2 GEMM (hid K=512), partials in g_fp (dstr=OUTN) ----
    for (int j = bid; j < 8; j += NBLK) {
        int nt = j >> 2, ks = j & 3;
        gemm64(g_hid, HH, HH, g_hid, 0,
               W_o2, HH, nt * 64, ks * 128, 128,
               g_fp + (size_t)ks * 64 * OUTN, OUTN, nullptr, sm.g);
    }
    gsync();
    // ---- E4: final reduce + bias + state copy ----
    for (int idx = bid * NTHR + tid; idx < BB * OUTN; idx += NBLK * NTHR) {
        int m = idx >> 7, u = idx & 127;
        float s = b_o2[u];
#pragma unroll
        for (int sl = 0; sl < 4; sl++)
            s += g_fp[(size_t)(sl * 64 + m) * OUTN + u];
        out[idx] = s;
    }
    if (write_state) {
        for (int idx = bid * NTHR + tid; idx < BB * HH; idx += NBLK * NTHR) {
            out[BB * OUTN + idx] = g_h[idx];
            out[BB * OUTN + BB * HH + idx] = g_c[idx];
        }
    }
}

// ============================================================================
extern "C" void kernel_launch(void* const* d_in, const int* in_sizes, int n_in,
                              void* d_out, int out_size) {
    const float* x       = (const float*)d_in[0];
    const float* h_en    = (const float*)d_in[1];
    const float* W_dec   = (const float*)d_in[2];
    const float* W_enc   = (const float*)d_in[3];
    const float* b_enc   = (const float*)d_in[4];
    const float* w_score = (const float*)d_in[5];
    const float* W_yattn = (const float*)d_in[6];
    const float* b_yattn = (const float*)d_in[7];
    const float* W_ih    = (const float*)d_in[8];
    const float* b_ih    = (const float*)d_in[9];
    const float* W_hh    = (const float*)d_in[10];
    const float* W_ff1   = (const float*)d_in[11];
    const float* b_ff1   = (const float*)d_in[12];
    const float* W_ff2   = (const float*)d_in[13];
    const float* b_ff2   = (const float*)d_in[14];
    const float* W_ta    = (const float*)d_in[15];
    const float* b_ta    = (const float*)d_in[16];
    const float* W_tb    = (const float*)d_in[17];
    const float* b_tb    = (const float*)d_in[18];
    const float* W_o1    = (const float*)d_in[19];
    const float* b_o1    = (const float*)d_in[20];
    const float* W_o2    = (const float*)d_in[21];
    const float* b_o2    = (const float*)d_in[22];
    float* out = (float*)d_out;

    int write_state = (out_size >= BB * OUTN + 2 * BB * HH) ? 1 : 0;

    k_pack<<<512, 256>>>(W_ih, W_hh, W_ff1, W_ff2, W_ta, W_tb,
                         b_ff1, b_ff2, b_ta, b_tb);
    k_main<<<NBLK, NTHR>>>(x, h_en, W_dec, W_enc, b_enc, w_score,
                           W_yattn, b_yattn, b_ih, W_o1, b_o1, W_o2, b_o2,
                           out, write_state);
}